// round 10
// baseline (speedup 1.0000x reference)
#include <cuda_runtime.h>
#include <math.h>
#include <stdint.h>

#define BATCH 16384
#define DIN 784
#define NH1 512
#define NH2 10
#define TSTEPS 20
#define SPLIT1 8
#define SPLIT2 64

#define THRESH 0.3f
#define DECAYF 0.3f
#define WDECAY 0.95f

// ---------------- device scratch (static globals: no allocations allowed) ----
__device__ float g_W1t[DIN * NH1];     // W1^T  [DIN][NH1]
__device__ float g_W2t[NH1 * NH2];     // W2^T  [NH1][NH2]
__device__ float g_hebb1[DIN * NH1];
__device__ float g_hebb2[NH1 * NH2];
__device__ float g_mem1[BATCH * NH1];
__device__ float g_h1s[BATCH * NH1];
__device__ float g_post1[BATCH * NH1];
__device__ float g_h1sum[BATCH * NH1];
__device__ float g_mem2[BATCH * NH2];
__device__ float g_h2s[BATCH * NH2];
__device__ float g_h2sum[BATCH * NH2];
__device__ float g_post2[BATCH * NH2];
__device__ float g_G1p[SPLIT1 * DIN * NH1];
__device__ float g_G2p[SPLIT2 * NH1 * NH2];

// ---------------- init: zero state, copy hebb inputs, transpose weights -----
__global__ void k_init(const float* __restrict__ hebb1_in,
                       const float* __restrict__ hebb2_in,
                       const float* __restrict__ W1,
                       const float* __restrict__ W2) {
    int i = blockIdx.x * blockDim.x + threadIdx.x;
    int stride = gridDim.x * blockDim.x;
    for (int j = i; j < BATCH * NH1; j += stride) {
        g_mem1[j] = 0.f; g_h1s[j] = 0.f; g_h1sum[j] = 0.f;
    }
    for (int j = i; j < BATCH * NH2; j += stride) {
        g_mem2[j] = 0.f; g_h2s[j] = 0.f; g_h2sum[j] = 0.f;
    }
    for (int j = i; j < DIN * NH1; j += stride) {
        g_hebb1[j] = hebb1_in[j];
        int d = j / NH1, h = j - d * NH1;
        g_W1t[j] = W1[h * DIN + d];
    }
    for (int j = i; j < NH1 * NH2; j += stride) {
        g_hebb2[j] = hebb2_in[j];
        int h = j / NH2, o = j - h * NH2;
        g_W2t[j] = W2[o * NH1 + h];
    }
}

// -- GEMM A: sumW = fl(x*df) @ W1t, sumH = fl(x*df) @ hebb1 (serial k FFMA) --
// state = ((sumW + b1) + alpha1*sumH); fused layer-1 elementwise update.
// C[16384,512], K=784. Tiles 128x64x16, 256 threads, 8x4 micro-tile.
__global__ void __launch_bounds__(256) k_gemmA(const float* __restrict__ x,
                                               const float* __restrict__ b1,
                                               const float* __restrict__ eta1,
                                               const float* __restrict__ alpha1,
                                               float arg) {
    float df = expf(arg);           // libdevice expf, matches XLA's exp emission
    __shared__ float xs[16][128];
    __shared__ float ws[16][64];
    __shared__ float hsm[16][64];
    int tid = threadIdx.x;
    int m0 = blockIdx.x * 128, n0 = blockIdx.y * 64;
    int ty = tid >> 4, tx = tid & 15;

    float accW[8][4], accH[8][4];
#pragma unroll
    for (int i = 0; i < 8; i++)
#pragma unroll
        for (int j = 0; j < 4; j++) { accW[i][j] = 0.f; accH[i][j] = 0.f; }

    int lr = tid >> 1;          // row 0..127 for x tile
    int lq = (tid & 1) * 2;     // float4 slot base
    int mk = tid >> 4;          // k row 0..15 for W/hebb tiles
    int mc = tid & 15;
    const float* xrow = x + (long long)(m0 + lr) * DIN;

    for (int k0 = 0; k0 < DIN; k0 += 16) {
#pragma unroll
        for (int l = 0; l < 2; l++) {
            float4 v = *(const float4*)(xrow + k0 + (lq + l) * 4);
            int kk = (lq + l) * 4;
            // x_in = fl(x*df), materialized once (reference order)
            xs[kk + 0][lr] = __fmul_rn(v.x, df);
            xs[kk + 1][lr] = __fmul_rn(v.y, df);
            xs[kk + 2][lr] = __fmul_rn(v.z, df);
            xs[kk + 3][lr] = __fmul_rn(v.w, df);
        }
        *(float4*)&ws[mk][mc * 4] =
            *(const float4*)(g_W1t + (k0 + mk) * NH1 + n0 + mc * 4);
        *(float4*)&hsm[mk][mc * 4] =
            *(const float4*)(g_hebb1 + (k0 + mk) * NH1 + n0 + mc * 4);
        __syncthreads();
#pragma unroll
        for (int k = 0; k < 16; k++) {
            float4 a0 = *(float4*)&xs[k][ty * 8];
            float4 a1 = *(float4*)&xs[k][ty * 8 + 4];
            float4 wv = *(float4*)&ws[k][tx * 4];
            float4 hv = *(float4*)&hsm[k][tx * 4];
            float ar[8] = {a0.x, a0.y, a0.z, a0.w, a1.x, a1.y, a1.z, a1.w};
            float wr[4] = {wv.x, wv.y, wv.z, wv.w};
            float hr[4] = {hv.x, hv.y, hv.z, hv.w};
#pragma unroll
            for (int i = 0; i < 8; i++)
#pragma unroll
                for (int j = 0; j < 4; j++) {
                    // two strictly-serial (ascending-k) FFMA chains, like sgemm
                    accW[i][j] = __fmaf_rn(ar[i], wr[j], accW[i][j]);
                    accH[i][j] = __fmaf_rn(ar[i], hr[j], accH[i][j]);
                }
        }
        __syncthreads();
    }

    // fused layer-1 elementwise update (explicitly rounded, no contraction)
    float a1s = __ldg(alpha1);
    float4 bv = *(const float4*)(b1 + n0 + tx * 4);
    float4 ev = *(const float4*)(eta1 + n0 + tx * 4);
    float bb[4] = {bv.x, bv.y, bv.z, bv.w};
    float ee[4] = {ev.x, ev.y, ev.z, ev.w};
#pragma unroll
    for (int i = 0; i < 8; i++) {
        int row = m0 + ty * 8 + i;
        int idx = row * NH1 + n0 + tx * 4;
        float4 mo = *(float4*)&g_mem1[idx];
        float4 so = *(float4*)&g_h1s[idx];
        float4 su = *(float4*)&g_h1sum[idx];
        float mold[4] = {mo.x, mo.y, mo.z, mo.w};
        float sold[4] = {so.x, so.y, so.z, so.w};
        float ssum[4] = {su.x, su.y, su.z, su.w};
        float nm[4], ns[4], np[4], nu[4];
#pragma unroll
        for (int j = 0; j < 4; j++) {
            // state = ((x@Wt) + b) + (alpha * (x@hebb))   [reference order]
            float state = __fadd_rn(__fadd_rn(accW[i][j], bb[j]),
                                    __fmul_rn(a1s, accH[i][j]));
            // mem = (mem - spike*thresh)*decay + state
            float m = __fadd_rn(
                __fmul_rn(__fsub_rn(mold[j], __fmul_rn(sold[j], THRESH)), DECAYF),
                state);
            float sp = __fsub_rn(m, THRESH) > 0.f ? 1.f : 0.f;
            float p = tanhf(__fsub_rn(__fdiv_rn(m, THRESH), ee[j]));
            nm[j] = m; ns[j] = sp; np[j] = p; nu[j] = __fadd_rn(ssum[j], sp);
        }
        *(float4*)&g_mem1[idx] = make_float4(nm[0], nm[1], nm[2], nm[3]);
        *(float4*)&g_h1s[idx]  = make_float4(ns[0], ns[1], ns[2], ns[3]);
        *(float4*)&g_post1[idx] = make_float4(np[0], np[1], np[2], np[3]);
        *(float4*)&g_h1sum[idx] = make_float4(nu[0], nu[1], nu[2], nu[3]);
    }
}

// ---------------- GEMM B: G1 = x^T @ post1, split-K partials ----------------
// C[784,512], K=16384 split into SPLIT1 chunks. Tiles 64x64x16, 4x4 micro.
__global__ void __launch_bounds__(256) k_gemmB(const float* __restrict__ x) {
    __shared__ float xs[16][64];
    __shared__ float ps[16][64];
    int tid = threadIdx.x;
    int i0 = blockIdx.x * 64, j0 = blockIdx.y * 64, z = blockIdx.z;
    int ty = tid >> 4, tx = tid & 15;
    int lk = tid >> 4, lc = tid & 15;
    float acc[4][4];
#pragma unroll
    for (int i = 0; i < 4; i++)
#pragma unroll
        for (int j = 0; j < 4; j++) acc[i][j] = 0.f;

    const int KCH = BATCH / SPLIT1;
    int kbase = z * KCH;
    bool valid = (i0 + lc * 4) < DIN;

    for (int kb = 0; kb < KCH; kb += 16) {
        int krow = kbase + kb + lk;
        float4 v = valid ? *(const float4*)(x + (long long)krow * DIN + i0 + lc * 4)
                         : make_float4(0.f, 0.f, 0.f, 0.f);
        *(float4*)&xs[lk][lc * 4] = v;
        *(float4*)&ps[lk][lc * 4] =
            *(const float4*)(g_post1 + (long long)krow * NH1 + j0 + lc * 4);
        __syncthreads();
#pragma unroll
        for (int k = 0; k < 16; k++) {
            float4 a = *(float4*)&xs[k][ty * 4];
            float4 b = *(float4*)&ps[k][tx * 4];
            float ar[4] = {a.x, a.y, a.z, a.w};
            float br[4] = {b.x, b.y, b.z, b.w};
#pragma unroll
            for (int i = 0; i < 4; i++)
#pragma unroll
                for (int j = 0; j < 4; j++)
                    acc[i][j] = __fmaf_rn(ar[i], br[j], acc[i][j]);
        }
        __syncthreads();
    }
    float* dst = g_G1p + (long long)z * (DIN * NH1);
#pragma unroll
    for (int i = 0; i < 4; i++) {
        int row = i0 + ty * 4 + i;
        if (row < DIN)
            *(float4*)&dst[row * NH1 + j0 + tx * 4] =
                make_float4(acc[i][0], acc[i][1], acc[i][2], acc[i][3]);
    }
}

// ---------------- reduce split-K + hebb1 update -----------------------------
__global__ void k_hebb1(const float* __restrict__ beta1, float arg) {
    float df = expf(arg);
    int j = blockIdx.x * blockDim.x + threadIdx.x;
    if (j >= DIN * NH1) return;
    float s = 0.f;
#pragma unroll
    for (int z = 0; z < SPLIT1; z++) s += g_G1p[z * (DIN * NH1) + j];
    int d = j / NH1;
    float term = __fmul_rn(__fmul_rn(__fmul_rn(__ldg(&beta1[d]), df), s),
                           1.f / BATCH);   // /16384 exact (power of 2)
    float h = __fadd_rn(__fmul_rn(WDECAY, g_hebb1[j]), term);
    g_hebb1[j] = fminf(fmaxf(h, -4.f), 4.f);
}

// -- layer 2: sumW = (h1s*df)@W2t, sumH = (h1s*df)@hebb2, serial k; fused ----
__global__ void __launch_bounds__(128) k_layer2(const float* __restrict__ b2,
                                                const float* __restrict__ eta2,
                                                const float* __restrict__ alpha2,
                                                float arg) {
    float df = expf(arg);   // h1s in {0,1}: fl(h1s*df) == h1s*df exact
    __shared__ float w2s[NH1 * 10];
    __shared__ float h2sm[NH1 * 10];
    for (int i = threadIdx.x; i < NH1 * NH2; i += 128) {
        w2s[i] = g_W2t[i];
        h2sm[i] = g_hebb2[i];
    }
    __syncthreads();
    int r0 = blockIdx.x * 256 + threadIdx.x;  // rows r0 and r0+128
    const float4* xa = (const float4*)(g_h1s + (long long)r0 * NH1);
    const float4* xb = (const float4*)(g_h1s + (long long)(r0 + 128) * NH1);
    float aW0[10], aH0[10], aW1[10], aH1[10];
#pragma unroll
    for (int j = 0; j < 10; j++) {
        aW0[j] = 0.f; aH0[j] = 0.f; aW1[j] = 0.f; aH1[j] = 0.f;
    }

    for (int k4 = 0; k4 < NH1 / 4; k4++) {
        float4 va = xa[k4], vb = xb[k4];
        float fa[4] = {va.x * df, va.y * df, va.z * df, va.w * df};
        float fb[4] = {vb.x * df, vb.y * df, vb.z * df, vb.w * df};
#pragma unroll
        for (int s = 0; s < 4; s++) {
            int k = k4 * 4 + s;
#pragma unroll
            for (int j = 0; j < 10; j++) {
                float w = w2s[k * 10 + j];
                float h = h2sm[k * 10 + j];
                aW0[j] = __fmaf_rn(fa[s], w, aW0[j]);
                aH0[j] = __fmaf_rn(fa[s], h, aH0[j]);
                aW1[j] = __fmaf_rn(fb[s], w, aW1[j]);
                aH1[j] = __fmaf_rn(fb[s], h, aH1[j]);
            }
        }
    }
    float a2s = __ldg(alpha2);
    float bb[10], ee[10];
#pragma unroll
    for (int j = 0; j < 10; j++) { bb[j] = b2[j]; ee[j] = eta2[j]; }

#pragma unroll
    for (int half = 0; half < 2; half++) {
        int r = r0 + half * 128;
        float* accW = half ? aW1 : aW0;
        float* accH = half ? aH1 : aH0;
#pragma unroll
        for (int j = 0; j < NH2; j++) {
            int idx = r * NH2 + j;
            float state = __fadd_rn(__fadd_rn(accW[j], bb[j]),
                                    __fmul_rn(a2s, accH[j]));
            float m = __fadd_rn(
                __fmul_rn(__fsub_rn(g_mem2[idx], __fmul_rn(g_h2s[idx], THRESH)),
                          DECAYF),
                state);
            float sp = __fsub_rn(m, THRESH) > 0.f ? 1.f : 0.f;
            float p = tanhf(__fsub_rn(__fdiv_rn(m, THRESH), ee[j]));
            g_mem2[idx] = m; g_h2s[idx] = sp; g_post2[idx] = p;
            g_h2sum[idx] = __fadd_rn(g_h2sum[idx], sp);
        }
    }
}

// ---------------- GEMM D: G2 = h1s^T @ post2, split-K partials --------------
__global__ void __launch_bounds__(256) k_gemmD() {
    __shared__ float ps[256 * 12];
    int tid = threadIdx.x;
    int r = blockIdx.x * 256 + tid;        // 0..511
    int k0 = blockIdx.y * 256;
    for (int i = tid; i < 256 * NH2; i += 256)
        ps[(i / NH2) * 12 + (i % NH2)] = g_post2[k0 * NH2 + i];
    for (int k = tid; k < 256; k += 256) {
        ps[k * 12 + 10] = 0.f; ps[k * 12 + 11] = 0.f;
    }
    __syncthreads();
    float acc[10];
#pragma unroll
    for (int j = 0; j < 10; j++) acc[j] = 0.f;
    for (int b = 0; b < 256; b++) {
        float h = g_h1s[(long long)(k0 + b) * NH1 + r];
        const float4* mr = (const float4*)&ps[b * 12];
        float4 m0 = mr[0], m1 = mr[1], m2v = mr[2];
        float mm[12] = {m0.x, m0.y, m0.z, m0.w, m1.x, m1.y, m1.z, m1.w,
                        m2v.x, m2v.y, m2v.z, m2v.w};
#pragma unroll
        for (int j = 0; j < 10; j++) acc[j] = __fmaf_rn(h, mm[j], acc[j]);
    }
    float* dst = g_G2p + blockIdx.y * (NH1 * NH2) + r * NH2;
#pragma unroll
    for (int j = 0; j < 10; j++) dst[j] = acc[j];
}

// ---------------- reduce split-K + hebb2 update -----------------------------
__global__ void k_hebb2(const float* __restrict__ beta2, float arg) {
    float df = expf(arg);
    int i = blockIdx.x * blockDim.x + threadIdx.x;
    if (i >= NH1 * NH2) return;
    float s = 0.f;
    for (int z = 0; z < SPLIT2; z++) s += g_G2p[z * (NH1 * NH2) + i];
    int r = i / NH2;
    float term = __fmul_rn(__fmul_rn(__fmul_rn(__ldg(&beta2[r]), df), s),
                           1.f / BATCH);
    float h = __fadd_rn(__fmul_rn(WDECAY, g_hebb2[i]), term);
    g_hebb2[i] = fminf(fmaxf(h, -4.f), 4.f);
}

// ---------------- final: pack outputs ---------------------------------------
__global__ void k_final(float* __restrict__ out, const float* __restrict__ eta1,
                        const float* __restrict__ eta2) {
    const int N0 = BATCH * NH2;
    const int N1 = N0 + BATCH * NH1;
    const int N2 = N1 + BATCH * NH2;
    const int N3 = N2 + DIN * NH1;
    const int N4 = N3 + NH1 * NH2;
    const int N5 = N4 + NH1;
    const int N6 = N5 + NH2;
    int i = blockIdx.x * blockDim.x + threadIdx.x;
    int stride = gridDim.x * blockDim.x;
    for (int j = i; j < N6; j += stride) {
        float v;
        if (j < N0)       v = fminf(__fdiv_rn(g_mem2[j], THRESH), 1.1f);
        else if (j < N1)  v = g_h1sum[j - N0];
        else if (j < N2)  v = g_h2sum[j - N1];
        else if (j < N3)  v = g_hebb1[j - N2];
        else if (j < N4)  v = g_hebb2[j - N3];
        else if (j < N5)  v = eta1[j - N4];
        else              v = eta2[j - N5];
        out[j] = v;
    }
}

// ---------------- host driver ------------------------------------------------
extern "C" void kernel_launch(void* const* d_in, const int* in_sizes, int n_in,
                              void* d_out, int out_size) {
    const float* x        = (const float*)d_in[0];
    const float* hebb1_in = (const float*)d_in[1];
    const float* hebb2_in = (const float*)d_in[2];
    const float* W1       = (const float*)d_in[3];
    const float* b1       = (const float*)d_in[4];
    const float* W2       = (const float*)d_in[5];
    const float* b2       = (const float*)d_in[6];
    const float* alpha1   = (const float*)d_in[7];
    const float* alpha2   = (const float*)d_in[8];
    const float* beta1    = (const float*)d_in[9];
    const float* beta2    = (const float*)d_in[10];
    const float* eta1     = (const float*)d_in[11];
    const float* eta2     = (const float*)d_in[12];

    k_init<<<2048, 256>>>(hebb1_in, hebb2_in, W1, W2);

    for (int t = 0; t < TSTEPS; t++) {
        // pass fl(-t/40); kernels compute df = expf(arg) via libdevice (as XLA does)
        float arg = -(float)t / 40.0f;
        k_gemmA<<<dim3(BATCH / 128, NH1 / 64), 256>>>(x, b1, eta1, alpha1, arg);
        k_gemmB<<<dim3((DIN + 63) / 64, NH1 / 64, SPLIT1), 256>>>(x);
        k_hebb1<<<(DIN * NH1 + 255) / 256, 256>>>(beta1, arg);
        k_layer2<<<BATCH / 256, 128>>>(b2, eta2, alpha2, arg);
        k_gemmD<<<dim3(NH1 / 256, SPLIT2), 256>>>();
        k_hebb2<<<(NH1 * NH2 + 255) / 256, 256>>>(beta2, arg);
    }

    k_final<<<4096, 256>>>((float*)d_out, eta1, eta2);
}

// round 12
// speedup vs baseline: 1.1252x; 1.1252x over previous
#include <cuda_runtime.h>
#include <math.h>
#include <stdint.h>

#define BATCH 16384
#define DIN 784
#define NH1 512
#define NH2 10
#define TSTEPS 20
#define SPLIT1 8
#define SPLIT2 64

#define THRESH 0.3f
#define DECAYF 0.3f
#define WDECAY 0.95f

typedef unsigned long long ull;

// packed f32x2 FMA: both halves exact IEEE fp32 fma.rn -> bit-identical chains
#define FMA2(d, a, b) \
    asm("fma.rn.f32x2 %0, %1, %2, %0;" : "+l"(d) : "l"(a), "l"(b))
// duplicate a scalar float into both lanes (alu-pipe mov, overlaps fma pipe)
#define PACKDUP(d, x) \
    asm("mov.b64 %0, {%1, %1};" : "=l"(d) : "r"(__float_as_uint(x)))

__device__ __forceinline__ float2 unpack2(ull v) {
    float2 r;
    uint32_t lo, hi;
    asm("mov.b64 {%0, %1}, %2;" : "=r"(lo), "=r"(hi) : "l"(v));
    r.x = __uint_as_float(lo); r.y = __uint_as_float(hi);
    return r;
}

// ---------------- device scratch (static globals: no allocations allowed) ----
__device__ float g_W1t[DIN * NH1];     // W1^T  [DIN][NH1]
__device__ float g_W2t[NH1 * NH2];     // W2^T  [NH1][NH2]
__device__ float g_hebb1[DIN * NH1];
__device__ float g_hebb2[NH1 * NH2];
__device__ float g_mem1[BATCH * NH1];
__device__ float g_h1s[BATCH * NH1];
__device__ float g_post1[BATCH * NH1];
__device__ float g_h1sum[BATCH * NH1];
__device__ float g_mem2[BATCH * NH2];
__device__ float g_h2s[BATCH * NH2];
__device__ float g_h2sum[BATCH * NH2];
__device__ float g_post2[BATCH * NH2];
__device__ float g_G1p[SPLIT1 * DIN * NH1];
__device__ float g_G2p[SPLIT2 * NH1 * NH2];

// ---------------- init: zero state, copy hebb inputs, transpose weights -----
__global__ void k_init(const float* __restrict__ hebb1_in,
                       const float* __restrict__ hebb2_in,
                       const float* __restrict__ W1,
                       const float* __restrict__ W2) {
    int i = blockIdx.x * blockDim.x + threadIdx.x;
    int stride = gridDim.x * blockDim.x;
    for (int j = i; j < BATCH * NH1; j += stride) {
        g_mem1[j] = 0.f; g_h1s[j] = 0.f; g_h1sum[j] = 0.f;
    }
    for (int j = i; j < BATCH * NH2; j += stride) {
        g_mem2[j] = 0.f; g_h2s[j] = 0.f; g_h2sum[j] = 0.f;
    }
    for (int j = i; j < DIN * NH1; j += stride) {
        g_hebb1[j] = hebb1_in[j];
        int d = j / NH1, h = j - d * NH1;
        g_W1t[j] = W1[h * DIN + d];
    }
    for (int j = i; j < NH1 * NH2; j += stride) {
        g_hebb2[j] = hebb2_in[j];
        int h = j / NH2, o = j - h * NH2;
        g_W2t[j] = W2[o * NH1 + h];
    }
}

// -- GEMM A: sumW = fl(x*df) @ W1t, sumH = fl(x*df) @ hebb1 ------------------
// f32x2-packed over adjacent N columns; each element's serial ascending-k
// fp32 fma.rn chain is bit-identical to the scalar version.
// C[16384,512], K=784. Tiles 128x64x16, 256 threads, 8x4 micro-tile.
__global__ void __launch_bounds__(256) k_gemmA(const float* __restrict__ x,
                                               const float* __restrict__ b1,
                                               const float* __restrict__ eta1,
                                               const float* __restrict__ alpha1,
                                               float arg) {
    float df = expf(arg);           // libdevice expf, matches XLA's exp emission
    __shared__ float xs[16][128];
    __shared__ float ws[16][64];
    __shared__ float hsm[16][64];
    int tid = threadIdx.x;
    int m0 = blockIdx.x * 128, n0 = blockIdx.y * 64;
    int ty = tid >> 4, tx = tid & 15;

    ull accW2[8][2], accH2[8][2];   // (j0,j1) and (j2,j3) packed pairs
#pragma unroll
    for (int i = 0; i < 8; i++) {
        accW2[i][0] = 0ull; accW2[i][1] = 0ull;
        accH2[i][0] = 0ull; accH2[i][1] = 0ull;
    }

    int lr = tid >> 1;          // row 0..127 for x tile
    int lq = (tid & 1) * 2;     // float4 slot base
    int mk = tid >> 4;          // k row 0..15 for W/hebb tiles
    int mc = tid & 15;
    const float* xrow = x + (long long)(m0 + lr) * DIN;

    for (int k0 = 0; k0 < DIN; k0 += 16) {
#pragma unroll
        for (int l = 0; l < 2; l++) {
            float4 v = *(const float4*)(xrow + k0 + (lq + l) * 4);
            int kk = (lq + l) * 4;
            // x_in = fl(x*df), materialized once (reference order)
            xs[kk + 0][lr] = __fmul_rn(v.x, df);
            xs[kk + 1][lr] = __fmul_rn(v.y, df);
            xs[kk + 2][lr] = __fmul_rn(v.z, df);
            xs[kk + 3][lr] = __fmul_rn(v.w, df);
        }
        *(float4*)&ws[mk][mc * 4] =
            *(const float4*)(g_W1t + (k0 + mk) * NH1 + n0 + mc * 4);
        *(float4*)&hsm[mk][mc * 4] =
            *(const float4*)(g_hebb1 + (k0 + mk) * NH1 + n0 + mc * 4);
        __syncthreads();
#pragma unroll
        for (int k = 0; k < 16; k++) {
            float4 a0 = *(float4*)&xs[k][ty * 8];
            float4 a1 = *(float4*)&xs[k][ty * 8 + 4];
            float ar[8] = {a0.x, a0.y, a0.z, a0.w, a1.x, a1.y, a1.z, a1.w};
            // adjacent-column pairs, 8-byte aligned smem reads
            ull w01 = *(const ull*)&ws[k][tx * 4];
            ull w23 = *(const ull*)&ws[k][tx * 4 + 2];
            ull h01 = *(const ull*)&hsm[k][tx * 4];
            ull h23 = *(const ull*)&hsm[k][tx * 4 + 2];
            ull ar2[8];
#pragma unroll
            for (int i = 0; i < 8; i++) PACKDUP(ar2[i], ar[i]);
#pragma unroll
            for (int i = 0; i < 8; i++) {
                FMA2(accW2[i][0], ar2[i], w01);
                FMA2(accW2[i][1], ar2[i], w23);
                FMA2(accH2[i][0], ar2[i], h01);
                FMA2(accH2[i][1], ar2[i], h23);
            }
        }
        __syncthreads();
    }

    // fused layer-1 elementwise update (explicitly rounded, no contraction)
    float a1s = __ldg(alpha1);
    float4 bv = *(const float4*)(b1 + n0 + tx * 4);
    float4 ev = *(const float4*)(eta1 + n0 + tx * 4);
    float bb[4] = {bv.x, bv.y, bv.z, bv.w};
    float ee[4] = {ev.x, ev.y, ev.z, ev.w};
#pragma unroll
    for (int i = 0; i < 8; i++) {
        int row = m0 + ty * 8 + i;
        int idx = row * NH1 + n0 + tx * 4;
        float2 w01 = unpack2(accW2[i][0]), w23 = unpack2(accW2[i][1]);
        float2 h01 = unpack2(accH2[i][0]), h23 = unpack2(accH2[i][1]);
        float accW[4] = {w01.x, w01.y, w23.x, w23.y};
        float accH[4] = {h01.x, h01.y, h23.x, h23.y};
        float4 mo = *(float4*)&g_mem1[idx];
        float4 so = *(float4*)&g_h1s[idx];
        float4 su = *(float4*)&g_h1sum[idx];
        float mold[4] = {mo.x, mo.y, mo.z, mo.w};
        float sold[4] = {so.x, so.y, so.z, so.w};
        float ssum[4] = {su.x, su.y, su.z, su.w};
        float nm[4], ns[4], np[4], nu[4];
#pragma unroll
        for (int j = 0; j < 4; j++) {
            // state = ((x@Wt) + b) + (alpha * (x@hebb))   [reference order]
            float state = __fadd_rn(__fadd_rn(accW[j], bb[j]),
                                    __fmul_rn(a1s, accH[j]));
            // mem = (mem - spike*thresh)*decay + state
            float m = __fadd_rn(
                __fmul_rn(__fsub_rn(mold[j], __fmul_rn(sold[j], THRESH)), DECAYF),
                state);
            float sp = __fsub_rn(m, THRESH) > 0.f ? 1.f : 0.f;
            float p = tanhf(__fsub_rn(__fdiv_rn(m, THRESH), ee[j]));
            nm[j] = m; ns[j] = sp; np[j] = p; nu[j] = __fadd_rn(ssum[j], sp);
        }
        *(float4*)&g_mem1[idx] = make_float4(nm[0], nm[1], nm[2], nm[3]);
        *(float4*)&g_h1s[idx]  = make_float4(ns[0], ns[1], ns[2], ns[3]);
        *(float4*)&g_post1[idx] = make_float4(np[0], np[1], np[2], np[3]);
        *(float4*)&g_h1sum[idx] = make_float4(nu[0], nu[1], nu[2], nu[3]);
    }
}

// ---------------- GEMM B: G1 = x^T @ post1, split-K partials, f32x2 ---------
// C[784,512], K=16384 split into SPLIT1 chunks. Tiles 64x64x16, 4x4 micro.
__global__ void __launch_bounds__(256) k_gemmB(const float* __restrict__ x) {
    __shared__ float xs[16][64];
    __shared__ float ps[16][64];
    int tid = threadIdx.x;
    int i0 = blockIdx.x * 64, j0 = blockIdx.y * 64, z = blockIdx.z;
    int ty = tid >> 4, tx = tid & 15;
    int lk = tid >> 4, lc = tid & 15;
    ull acc2[4][2];
#pragma unroll
    for (int i = 0; i < 4; i++) { acc2[i][0] = 0ull; acc2[i][1] = 0ull; }

    const int KCH = BATCH / SPLIT1;
    int kbase = z * KCH;
    bool valid = (i0 + lc * 4) < DIN;

    for (int kb = 0; kb < KCH; kb += 16) {
        int krow = kbase + kb + lk;
        float4 v = valid ? *(const float4*)(x + (long long)krow * DIN + i0 + lc * 4)
                         : make_float4(0.f, 0.f, 0.f, 0.f);
        *(float4*)&xs[lk][lc * 4] = v;
        *(float4*)&ps[lk][lc * 4] =
            *(const float4*)(g_post1 + (long long)krow * NH1 + j0 + lc * 4);
        __syncthreads();
#pragma unroll
        for (int k = 0; k < 16; k++) {
            float4 a = *(float4*)&xs[k][ty * 4];
            float ar[4] = {a.x, a.y, a.z, a.w};
            ull b01 = *(const ull*)&ps[k][tx * 4];
            ull b23 = *(const ull*)&ps[k][tx * 4 + 2];
            ull ar2[4];
#pragma unroll
            for (int i = 0; i < 4; i++) PACKDUP(ar2[i], ar[i]);
#pragma unroll
            for (int i = 0; i < 4; i++) {
                FMA2(acc2[i][0], ar2[i], b01);
                FMA2(acc2[i][1], ar2[i], b23);
            }
        }
        __syncthreads();
    }
    float* dst = g_G1p + (long long)z * (DIN * NH1);
#pragma unroll
    for (int i = 0; i < 4; i++) {
        int row = i0 + ty * 4 + i;
        if (row < DIN) {
            float2 p01 = unpack2(acc2[i][0]), p23 = unpack2(acc2[i][1]);
            *(float4*)&dst[row * NH1 + j0 + tx * 4] =
                make_float4(p01.x, p01.y, p23.x, p23.y);
        }
    }
}

// ---------------- reduce split-K + hebb1 update -----------------------------
__global__ void k_hebb1(const float* __restrict__ beta1, float arg) {
    float df = expf(arg);
    int j = blockIdx.x * blockDim.x + threadIdx.x;
    if (j >= DIN * NH1) return;
    float s = 0.f;
#pragma unroll
    for (int z = 0; z < SPLIT1; z++) s += g_G1p[z * (DIN * NH1) + j];
    int d = j / NH1;
    float term = __fmul_rn(__fmul_rn(__fmul_rn(__ldg(&beta1[d]), df), s),
                           1.f / BATCH);   // /16384 exact (power of 2)
    float h = __fadd_rn(__fmul_rn(WDECAY, g_hebb1[j]), term);
    g_hebb1[j] = fminf(fmaxf(h, -4.f), 4.f);
}

// -- layer 2: sumW = (h1s*df)@W2t, sumH = (h1s*df)@hebb2, f32x2 pairs --------
// 128 blocks x 128 threads, one batch row per thread (better occupancy).
__global__ void __launch_bounds__(128) k_layer2(const float* __restrict__ b2,
                                                const float* __restrict__ eta2,
                                                const float* __restrict__ alpha2,
                                                float arg) {
    float df = expf(arg);   // h1s in {0,1}: fl(h1s*df) == h1s*df exact
    __shared__ float w2s[NH1 * 10];
    __shared__ float h2sm[NH1 * 10];
    for (int i = threadIdx.x; i < NH1 * NH2; i += 128) {
        w2s[i] = g_W2t[i];
        h2sm[i] = g_hebb2[i];
    }
    __syncthreads();
    int r = blockIdx.x * 128 + threadIdx.x;   // 0..16383
    const float4* xa = (const float4*)(g_h1s + (long long)r * NH1);
    ull aW2[5], aH2[5];
#pragma unroll
    for (int j = 0; j < 5; j++) { aW2[j] = 0ull; aH2[j] = 0ull; }

    for (int k4 = 0; k4 < NH1 / 4; k4++) {
        float4 va = xa[k4];
        float fa[4] = {va.x * df, va.y * df, va.z * df, va.w * df};
#pragma unroll
        for (int s = 0; s < 4; s++) {
            int k = k4 * 4 + s;
            ull fa2; PACKDUP(fa2, fa[s]);
            // rows are 40 bytes (10 floats): 8-byte aligned; pairs aligned
            const ull* wrow = (const ull*)&w2s[k * 10];
            const ull* hrow = (const ull*)&h2sm[k * 10];
#pragma unroll
            for (int j = 0; j < 5; j++) {
                FMA2(aW2[j], fa2, wrow[j]);
                FMA2(aH2[j], fa2, hrow[j]);
            }
        }
    }
    float accW[10], accH[10];
#pragma unroll
    for (int j = 0; j < 5; j++) {
        float2 w = unpack2(aW2[j]), h = unpack2(aH2[j]);
        accW[2 * j] = w.x; accW[2 * j + 1] = w.y;
        accH[2 * j] = h.x; accH[2 * j + 1] = h.y;
    }
    float a2s = __ldg(alpha2);
#pragma unroll
    for (int j = 0; j < NH2; j++) {
        int idx = r * NH2 + j;
        float state = __fadd_rn(__fadd_rn(accW[j], b2[j]),
                                __fmul_rn(a2s, accH[j]));
        float m = __fadd_rn(
            __fmul_rn(__fsub_rn(g_mem2[idx], __fmul_rn(g_h2s[idx], THRESH)),
                      DECAYF),
            state);
        float sp = __fsub_rn(m, THRESH) > 0.f ? 1.f : 0.f;
        float p = tanhf(__fsub_rn(__fdiv_rn(m, THRESH), eta2[j]));
        g_mem2[idx] = m; g_h2s[idx] = sp; g_post2[idx] = p;
        g_h2sum[idx] = __fadd_rn(g_h2sum[idx], sp);
    }
}

// ---------------- GEMM D: G2 = h1s^T @ post2, split-K partials, f32x2 -------
__global__ void __launch_bounds__(256) k_gemmD() {
    __shared__ float ps[256 * 12];
    int tid = threadIdx.x;
    int r = blockIdx.x * 256 + tid;        // 0..511
    int k0 = blockIdx.y * 256;
    for (int i = tid; i < 256 * NH2; i += 256)
        ps[(i / NH2) * 12 + (i % NH2)] = g_post2[k0 * NH2 + i];
    for (int k = tid; k < 256; k += 256) {
        ps[k * 12 + 10] = 0.f; ps[k * 12 + 11] = 0.f;
    }
    __syncthreads();
    ull acc2[5];
#pragma unroll
    for (int j = 0; j < 5; j++) acc2[j] = 0ull;
    for (int b = 0; b < 256; b++) {
        float h = g_h1s[(long long)(k0 + b) * NH1 + r];
        ull h2; PACKDUP(h2, h);
        // rows 48 bytes: 8-byte aligned pairs
        const ull* prow = (const ull*)&ps[b * 12];
#pragma unroll
        for (int j = 0; j < 5; j++) FMA2(acc2[j], h2, prow[j]);
    }
    float* dst = g_G2p + blockIdx.y * (NH1 * NH2) + r * NH2;
#pragma unroll
    for (int j = 0; j < 5; j++) {
        float2 v = unpack2(acc2[j]);
        dst[2 * j] = v.x; dst[2 * j + 1] = v.y;
    }
}

// ---------------- reduce split-K + hebb2 update -----------------------------
__global__ void k_hebb2(const float* __restrict__ beta2, float arg) {
    float df = expf(arg);
    int i = blockIdx.x * blockDim.x + threadIdx.x;
    if (i >= NH1 * NH2) return;
    float s = 0.f;
    for (int z = 0; z < SPLIT2; z++) s += g_G2p[z * (NH1 * NH2) + i];
    int r = i / NH2;
    float term = __fmul_rn(__fmul_rn(__fmul_rn(__ldg(&beta2[r]), df), s),
                           1.f / BATCH);
    float h = __fadd_rn(__fmul_rn(WDECAY, g_hebb2[i]), term);
    g_hebb2[i] = fminf(fmaxf(h, -4.f), 4.f);
}

// ---------------- final: pack outputs ---------------------------------------
__global__ void k_final(float* __restrict__ out, const float* __restrict__ eta1,
                        const float* __restrict__ eta2) {
    const int N0 = BATCH * NH2;
    const int N1 = N0 + BATCH * NH1;
    const int N2 = N1 + BATCH * NH2;
    const int N3 = N2 + DIN * NH1;
    const int N4 = N3 + NH1 * NH2;
    const int N5 = N4 + NH1;
    const int N6 = N5 + NH2;
    int i = blockIdx.x * blockDim.x + threadIdx.x;
    int stride = gridDim.x * blockDim.x;
    for (int j = i; j < N6; j += stride) {
        float v;
        if (j < N0)       v = fminf(__fdiv_rn(g_mem2[j], THRESH), 1.1f);
        else if (j < N1)  v = g_h1sum[j - N0];
        else if (j < N2)  v = g_h2sum[j - N1];
        else if (j < N3)  v = g_hebb1[j - N2];
        else if (j < N4)  v = g_hebb2[j - N3];
        else if (j < N5)  v = eta1[j - N4];
        else              v = eta2[j - N5];
        out[j] = v;
    }
}

// ---------------- host driver ------------------------------------------------
extern "C" void kernel_launch(void* const* d_in, const int* in_sizes, int n_in,
                              void* d_out, int out_size) {
    const float* x        = (const float*)d_in[0];
    const float* hebb1_in = (const float*)d_in[1];
    const float* hebb2_in = (const float*)d_in[2];
    const float* W1       = (const float*)d_in[3];
    const float* b1       = (const float*)d_in[4];
    const float* W2       = (const float*)d_in[5];
    const float* b2       = (const float*)d_in[6];
    const float* alpha1   = (const float*)d_in[7];
    const float* alpha2   = (const float*)d_in[8];
    const float* beta1    = (const float*)d_in[9];
    const float* beta2    = (const float*)d_in[10];
    const float* eta1     = (const float*)d_in[11];
    const float* eta2     = (const float*)d_in[12];

    k_init<<<2048, 256>>>(hebb1_in, hebb2_in, W1, W2);

    for (int t = 0; t < TSTEPS; t++) {
        // pass fl(-t/40); kernels compute df = expf(arg) via libdevice (as XLA does)
        float arg = -(float)t / 40.0f;
        k_gemmA<<<dim3(BATCH / 128, NH1 / 64), 256>>>(x, b1, eta1, alpha1, arg);
        k_gemmB<<<dim3((DIN + 63) / 64, NH1 / 64, SPLIT1), 256>>>(x);
        k_hebb1<<<(DIN * NH1 + 255) / 256, 256>>>(beta1, arg);
        k_layer2<<<BATCH / 128, 128>>>(b2, eta2, alpha2, arg);
        k_gemmD<<<dim3(NH1 / 256, SPLIT2), 256>>>();
        k_hebb2<<<(NH1 * NH2 + 255) / 256, 256>>>(beta2, arg);
    }

    k_final<<<4096, 256>>>((float*)d_out, eta1, eta2);
}